// round 4
// baseline (speedup 1.0000x reference)
#include <cuda_runtime.h>
#include <cuda_bf16.h>

// PatchFFTLoss round 4: 4 threads per patch, rows {t, t+4} per thread.
//  - z = (input + i*target)/16, one complex 8x8 FFT, Hermitian separation.
//  - column FFT: stage 1 (dist 4) in-register; stage 2 (xor 2) and stage 3
//    (xor 1) cross-lane. Lane t ends with bins uA = [0,4,2,6][t] (even chain)
//    and uB = [1,5,3,7][t] (odd chain).
//  - conjugate symmetry: only v=0..4 evaluated, weights per (u,v).
//  - halved register footprint vs round 3 (32 live floats) -> 3 CTAs/SM.
//  - fused last-block-done reduction, bit-deterministic, graph-capturable.

#define NPATCH   (16 * 3 * 64 * 64)       // 196608
#define NTHREADS (NPATCH * 4)             // 786432
#define BLOCK    256
#define NBLOCKS  (NTHREADS / BLOCK)       // 3072
#define LN2      0.69314718055994530942f
#define FINAL_SCALE ((LN2 * LN2) / 12582912.0f)
#define FULLM    0xffffffffu

__device__ float g_partials[NBLOCKS];
__device__ unsigned int g_count = 0;

__device__ __forceinline__ float sgnlg2(float x) {
    return copysignf(__log2f(1.0f + fabsf(x)), x);
}

// loss cell: Z at (u,v), Zn = Z at (-u,-v); recovers Fi, Ft (1/2 in load scale)
__device__ __forceinline__ float cell(float Zr_, float Zi_, float Znr, float Zni) {
    float fir = Zr_ + Znr;
    float fii = Zi_ - Zni;
    float ftr = Zi_ + Zni;
    float fti = Znr - Zr_;
    float d1 = sgnlg2(fir) - sgnlg2(ftr);
    float d2 = sgnlg2(fii) - sgnlg2(fti);
    return fmaf(d1, d1, d2 * d2);
}

// 8-pt complex FFT, natural-order output bins (validated rounds 2-3)
__device__ __forceinline__ void rowfft(const float zr[8], const float zi[8],
                                       float Xr[8], float Xi[8]) {
    const float C = 0.70710678118654752440f;
    float A0r=zr[0]+zr[4], A0i=zi[0]+zi[4];
    float A1r=zr[1]+zr[5], A1i=zi[1]+zi[5];
    float A2r=zr[2]+zr[6], A2i=zi[2]+zi[6];
    float A3r=zr[3]+zr[7], A3i=zi[3]+zi[7];
    float B0r=zr[0]-zr[4], B0i=zi[0]-zi[4];
    float d1r=zr[1]-zr[5], d1i=zi[1]-zi[5];
    float B1r=C*(d1r+d1i), B1i=C*(d1i-d1r);
    float B2r=zi[2]-zi[6], B2i=zr[6]-zr[2];
    float d3r=zr[3]-zr[7], d3i=zi[3]-zi[7];
    float B3r=C*(d3i-d3r), B3i=-C*(d3r+d3i);

    float A20r=A0r+A2r, A20i=A0i+A2i;
    float A22r=A0r-A2r, A22i=A0i-A2i;
    float A21r=A1r+A3r, A21i=A1i+A3i;
    float A23r=A1i-A3i, A23i=A3r-A1r;
    float B20r=B0r+B2r, B20i=B0i+B2i;
    float B22r=B0r-B2r, B22i=B0i-B2i;
    float B21r=B1r+B3r, B21i=B1i+B3i;
    float B23r=B1i-B3i, B23i=B3r-B1r;

    Xr[0]=A20r+A21r; Xi[0]=A20i+A21i;
    Xr[4]=A20r-A21r; Xi[4]=A20i-A21i;
    Xr[2]=A22r+A23r; Xi[2]=A22i+A23i;
    Xr[6]=A22r-A23r; Xi[6]=A22i-A23i;
    Xr[1]=B20r+B21r; Xi[1]=B20i+B21i;
    Xr[5]=B20r-B21r; Xi[5]=B20i-B21i;
    Xr[3]=B22r+B23r; Xi[3]=B22i+B23i;
    Xr[7]=B22r-B23r; Xi[7]=B22i-B23i;
}

__global__ void __launch_bounds__(BLOCK, 3)
patch_fft_loss_kernel(const float* __restrict__ inp,
                      const float* __restrict__ tgt,
                      float* __restrict__ out)
{
    const int gid = blockIdx.x * BLOCK + threadIdx.x;
    const int t  = gid & 3;           // lane within 4-lane patch group
    const int p  = gid >> 2;
    const int pw = p & 63;
    const int ph = (p >> 6) & 63;
    const int bc = p >> 12;

    const float C = 0.70710678118654752440f;
    const size_t base = ((size_t)(bc * 512 + ph * 8 + t)) * 512 + (size_t)pw * 8;

    // ---- load rows t and t+4 (both tensors), row FFT each ----
    float Ar[8], Ai[8], Br[8], Bi[8];   // A/B hold F0/F1, then chains in-place
    {
        float4 a0 = *(const float4*)(inp + base);
        float4 b0 = *(const float4*)(inp + base + 4);
        float4 c0 = *(const float4*)(tgt + base);
        float4 d0 = *(const float4*)(tgt + base + 4);
        float4 a1 = *(const float4*)(inp + base + 2048);
        float4 b1 = *(const float4*)(inp + base + 2052);
        float4 c1 = *(const float4*)(tgt + base + 2048);
        float4 d1 = *(const float4*)(tgt + base + 2052);
        float zr[8], zi[8];
        zr[0]=a0.x*0.0625f; zr[1]=a0.y*0.0625f; zr[2]=a0.z*0.0625f; zr[3]=a0.w*0.0625f;
        zr[4]=b0.x*0.0625f; zr[5]=b0.y*0.0625f; zr[6]=b0.z*0.0625f; zr[7]=b0.w*0.0625f;
        zi[0]=c0.x*0.0625f; zi[1]=c0.y*0.0625f; zi[2]=c0.z*0.0625f; zi[3]=c0.w*0.0625f;
        zi[4]=d0.x*0.0625f; zi[5]=d0.y*0.0625f; zi[6]=d0.z*0.0625f; zi[7]=d0.w*0.0625f;
        rowfft(zr, zi, Ar, Ai);                       // F0 = row t
        zr[0]=a1.x*0.0625f; zr[1]=a1.y*0.0625f; zr[2]=a1.z*0.0625f; zr[3]=a1.w*0.0625f;
        zr[4]=b1.x*0.0625f; zr[5]=b1.y*0.0625f; zr[6]=b1.z*0.0625f; zr[7]=b1.w*0.0625f;
        zi[0]=c1.x*0.0625f; zi[1]=c1.y*0.0625f; zi[2]=c1.z*0.0625f; zi[3]=c1.w*0.0625f;
        zi[4]=d1.x*0.0625f; zi[5]=d1.y*0.0625f; zi[6]=d1.z*0.0625f; zi[7]=d1.w*0.0625f;
        rowfft(zr, zi, Br, Bi);                       // F1 = row t+4
    }

    // per-lane constants
    // stage1 twiddle W8^t: (1,0),(C,-C),(0,-1),(-C,-C)
    const float w1r = (t==0)?1.0f:(t==1)?C:(t==2)?0.0f:-C;
    const float w1i = (t==0)?0.0f:((t==2)?-1.0f:-C);
    const float s2  = (t < 2) ? 1.0f : -1.0f;
    // stage2 post-twiddle: identity except t==3 -> W4^1 = (0,-1)
    const float wSr = (t==3)?0.0f:1.0f;
    const float wSi = (t==3)?-1.0f:0.0f;
    const float s3  = (t & 1) ? -1.0f : 1.0f;

    #pragma unroll
    for (int v = 0; v < 8; v++) {
        // ---- stage 1 (dist 4, in-register): A = F0+F1 ; B = (F0-F1)*W8^t ----
        float ar = Ar[v] + Br[v], ai = Ai[v] + Bi[v];
        float er = Ar[v] - Br[v], ei = Ai[v] - Bi[v];
        float br = fmaf(er, w1r, -ei * w1i);
        float bi = fmaf(er, w1i,  ei * w1r);
        // ---- stage 2 (xor 2): lanes<2: own+peer ; lanes>=2: (peer-own)*wS ----
        float pr, pi, sr, si;
        pr = __shfl_xor_sync(FULLM, ar, 2);
        pi = __shfl_xor_sync(FULLM, ai, 2);
        sr = fmaf(s2, ar, pr); si = fmaf(s2, ai, pi);
        ar = fmaf(sr, wSr, -si * wSi);
        ai = fmaf(sr, wSi,  si * wSr);
        pr = __shfl_xor_sync(FULLM, br, 2);
        pi = __shfl_xor_sync(FULLM, bi, 2);
        sr = fmaf(s2, br, pr); si = fmaf(s2, bi, pi);
        br = fmaf(sr, wSr, -si * wSi);
        bi = fmaf(sr, wSi,  si * wSr);
        // ---- stage 3 (xor 1): even: own+peer ; odd: peer-own ----
        pr = __shfl_xor_sync(FULLM, ar, 1);
        pi = __shfl_xor_sync(FULLM, ai, 1);
        Ar[v] = fmaf(s3, ar, pr);
        Ai[v] = fmaf(s3, ai, pi);
        pr = __shfl_xor_sync(FULLM, br, 1);
        pi = __shfl_xor_sync(FULLM, bi, 1);
        Br[v] = fmaf(s3, br, pr);
        Bi[v] = fmaf(s3, bi, pi);
    }
    // lane t now owns column-bin uA = [0,4,2,6][t] (A) and uB = [1,5,3,7][t] (B)

    // ---- Hermitian separation + loss over canonical half (v = 0..4) ----
    // conj-partner lanes (within 4-group): A: sigma = t ^ (t>>1); B: 3 - t
    const int sA = t ^ (t >> 1);
    const int sB = t ^ 3;
    // v in {0,4} weights: u in {0,4} -> 1, u in {1,2,3} -> 2, u in {5,6,7} -> 0
    const float wA04 = (t < 2) ? 1.0f : ((t == 2) ? 2.0f : 0.0f);
    const float wB04 = ((t & 1) == 0) ? 2.0f : 0.0f;

    float acc1 = 0.0f, acc2 = 0.0f;
    #pragma unroll
    for (int v = 0; v <= 4; v++) {
        const int vp = (8 - v) & 7;
        float anr = __shfl_sync(FULLM, Ar[vp], sA, 4);
        float ani = __shfl_sync(FULLM, Ai[vp], sA, 4);
        float lA = cell(Ar[v], Ai[v], anr, ani);
        float bnr = __shfl_sync(FULLM, Br[vp], sB, 4);
        float bni = __shfl_sync(FULLM, Bi[vp], sB, 4);
        float lB = cell(Br[v], Bi[v], bnr, bni);
        if (v == 0 || v == 4) {
            acc1 = fmaf(wA04, lA, acc1);
            acc1 = fmaf(wB04, lB, acc1);
        } else {
            acc2 += lA + lB;
        }
    }
    float acc = fmaf(2.0f, acc2, acc1);

    // ---- deterministic reduction: warp -> block -> last-block-done global ----
    #pragma unroll
    for (int o = 16; o > 0; o >>= 1)
        acc += __shfl_xor_sync(FULLM, acc, o);

    __shared__ float smw[BLOCK / 32];
    __shared__ bool isLast;
    if ((threadIdx.x & 31) == 0) smw[threadIdx.x >> 5] = acc;
    __syncthreads();
    if (threadIdx.x == 0) {
        float s = 0.0f;
        #pragma unroll
        for (int i = 0; i < BLOCK / 32; i++) s += smw[i];
        g_partials[blockIdx.x] = s;
        __threadfence();
        unsigned old = atomicInc(&g_count, NBLOCKS - 1);  // wraps to 0 on last
        isLast = (old == NBLOCKS - 1);
    }
    __syncthreads();

    if (isLast) {
        float a = 0.0f;
        #pragma unroll
        for (int i = 0; i < NBLOCKS / BLOCK; i++)
            a += __ldcg(&g_partials[threadIdx.x + i * BLOCK]);
        #pragma unroll
        for (int o = 16; o > 0; o >>= 1)
            a += __shfl_xor_sync(FULLM, a, o);
        if ((threadIdx.x & 31) == 0) smw[threadIdx.x >> 5] = a;
        __syncthreads();
        if (threadIdx.x == 0) {
            float s = 0.0f;
            #pragma unroll
            for (int i = 0; i < BLOCK / 32; i++) s += smw[i];
            out[0] = s * FINAL_SCALE;
        }
    }
}

extern "C" void kernel_launch(void* const* d_in, const int* in_sizes, int n_in,
                              void* d_out, int out_size)
{
    const float* inp = (const float*)d_in[0];
    const float* tgt = (const float*)d_in[1];
    patch_fft_loss_kernel<<<NBLOCKS, BLOCK>>>(inp, tgt, (float*)d_out);
}

// round 5
// speedup vs baseline: 1.4735x; 1.4735x over previous
#include <cuda_runtime.h>
#include <cuda_bf16.h>

// PatchFFTLoss round 5: ONE thread per patch, zero shuffles.
//  - z = (input + i*target)/16, 8 row FFTs + 8 column FFTs fully in registers.
//  - Hermitian separation per conjugate pair (u,v)<->(-u,-v), all in-register.
//  - conjugate symmetry: 30 paired cells (weight 2) + 4 self cells (weight 1).
//  - fused last-block-done reduction, bit-deterministic, graph-capturable.

#define NPATCH   (16 * 3 * 64 * 64)       // 196608
#define BLOCK    128
#define NBLOCKS  (NPATCH / BLOCK)         // 1536
#define LN2      0.69314718055994530942f
#define FINAL_SCALE ((LN2 * LN2) / 12582912.0f)
#define FULLM    0xffffffffu

__device__ float g_partials[NBLOCKS];
__device__ unsigned int g_count = 0;

__device__ __forceinline__ float sgnlg2(float x) {
    return copysignf(__log2f(1.0f + fabsf(x)), x);
}

// loss cell: Z at (u,v), Zn = Z at (-u,-v); Fi = (Z+conj Zn), Ft = -i(Z-conj Zn)
// (the 1/2 is folded into the load scale). Self-conjugate bins: pass Zn = Z.
__device__ __forceinline__ float cell(float Zr_, float Zi_, float Znr, float Zni) {
    float fir = Zr_ + Znr;
    float fii = Zi_ - Zni;
    float ftr = Zi_ + Zni;
    float fti = Znr - Zr_;
    float d1 = sgnlg2(fir) - sgnlg2(ftr);
    float d2 = sgnlg2(fii) - sgnlg2(fti);
    return fmaf(d1, d1, d2 * d2);
}

// in-place 8-pt complex FFT, natural-order bins (network validated rounds 2-4)
__device__ __forceinline__ void fft8(
    float& x0r, float& x1r, float& x2r, float& x3r,
    float& x4r, float& x5r, float& x6r, float& x7r,
    float& x0i, float& x1i, float& x2i, float& x3i,
    float& x4i, float& x5i, float& x6i, float& x7i)
{
    const float C = 0.70710678118654752440f;
    float A0r=x0r+x4r, A0i=x0i+x4i;
    float A1r=x1r+x5r, A1i=x1i+x5i;
    float A2r=x2r+x6r, A2i=x2i+x6i;
    float A3r=x3r+x7r, A3i=x3i+x7i;
    float B0r=x0r-x4r, B0i=x0i-x4i;
    float d1r=x1r-x5r, d1i=x1i-x5i;
    float B1r=C*(d1r+d1i), B1i=C*(d1i-d1r);
    float B2r=x2i-x6i,     B2i=x6r-x2r;
    float d3r=x3r-x7r, d3i=x3i-x7i;
    float B3r=C*(d3i-d3r), B3i=-C*(d3r+d3i);

    float A20r=A0r+A2r, A20i=A0i+A2i;
    float A22r=A0r-A2r, A22i=A0i-A2i;
    float A21r=A1r+A3r, A21i=A1i+A3i;
    float A23r=A1i-A3i, A23i=A3r-A1r;
    float B20r=B0r+B2r, B20i=B0i+B2i;
    float B22r=B0r-B2r, B22i=B0i-B2i;
    float B21r=B1r+B3r, B21i=B1i+B3i;
    float B23r=B1i-B3i, B23i=B3r-B1r;

    x0r=A20r+A21r; x0i=A20i+A21i;
    x4r=A20r-A21r; x4i=A20i-A21i;
    x2r=A22r+A23r; x2i=A22i+A23i;
    x6r=A22r-A23r; x6i=A22i-A23i;
    x1r=B20r+B21r; x1i=B20i+B21i;
    x5r=B20r-B21r; x5i=B20i-B21i;
    x3r=B22r+B23r; x3i=B22i+B23i;
    x7r=B22r-B23r; x7i=B22i-B23i;
}

__global__ void __launch_bounds__(BLOCK, 3)
patch_fft_loss_kernel(const float* __restrict__ inp,
                      const float* __restrict__ tgt,
                      float* __restrict__ out)
{
    const int p  = blockIdx.x * BLOCK + threadIdx.x;   // patch index
    const int pw = p & 63;
    const int ph = (p >> 6) & 63;
    const int bc = p >> 12;
    const size_t base = ((size_t)(bc * 512 + ph * 8)) * 512 + (size_t)pw * 8;

    // Z[u][v]: packed complex patch, fully register-resident (128 floats)
    float Zr[8][8], Zi[8][8];

    // ---- phase 1: load + scale + row FFT, one row at a time ----
    #pragma unroll
    for (int r = 0; r < 8; r++) {
        const float* ip = inp + base + (size_t)r * 512;
        const float* tp = tgt + base + (size_t)r * 512;
        float4 a = *(const float4*)(ip);
        float4 b = *(const float4*)(ip + 4);
        float4 c = *(const float4*)(tp);
        float4 d = *(const float4*)(tp + 4);
        Zr[r][0]=a.x*0.0625f; Zr[r][1]=a.y*0.0625f; Zr[r][2]=a.z*0.0625f; Zr[r][3]=a.w*0.0625f;
        Zr[r][4]=b.x*0.0625f; Zr[r][5]=b.y*0.0625f; Zr[r][6]=b.z*0.0625f; Zr[r][7]=b.w*0.0625f;
        Zi[r][0]=c.x*0.0625f; Zi[r][1]=c.y*0.0625f; Zi[r][2]=c.z*0.0625f; Zi[r][3]=c.w*0.0625f;
        Zi[r][4]=d.x*0.0625f; Zi[r][5]=d.y*0.0625f; Zi[r][6]=d.z*0.0625f; Zi[r][7]=d.w*0.0625f;
        fft8(Zr[r][0],Zr[r][1],Zr[r][2],Zr[r][3],Zr[r][4],Zr[r][5],Zr[r][6],Zr[r][7],
             Zi[r][0],Zi[r][1],Zi[r][2],Zi[r][3],Zi[r][4],Zi[r][5],Zi[r][6],Zi[r][7]);
    }

    // ---- phase 2: column FFTs (over u) ----
    #pragma unroll
    for (int v = 0; v < 8; v++) {
        fft8(Zr[0][v],Zr[1][v],Zr[2][v],Zr[3][v],Zr[4][v],Zr[5][v],Zr[6][v],Zr[7][v],
             Zi[0][v],Zi[1][v],Zi[2][v],Zi[3][v],Zi[4][v],Zi[5][v],Zi[6][v],Zi[7][v]);
    }

    // ---- phase 3: Hermitian separation + loss over canonical half ----
    float acc1 = 0.0f, acc2 = 0.0f;
    // 4 self-conjugate bins (weight 1); cell(Z,Z) doubles fir/ftr which fixes scale
    acc1 += cell(Zr[0][0], Zi[0][0], Zr[0][0], Zi[0][0]);
    acc1 += cell(Zr[0][4], Zi[0][4], Zr[0][4], Zi[0][4]);
    acc1 += cell(Zr[4][0], Zi[4][0], Zr[4][0], Zi[4][0]);
    acc1 += cell(Zr[4][4], Zi[4][4], Zr[4][4], Zi[4][4]);
    // v = 1..3, all u: 24 paired cells (weight 2)
    #pragma unroll
    for (int v = 1; v <= 3; v++) {
        #pragma unroll
        for (int u = 0; u < 8; u++) {
            const int un = (8 - u) & 7;
            const int vn = 8 - v;
            acc2 += cell(Zr[u][v], Zi[u][v], Zr[un][vn], Zi[un][vn]);
        }
    }
    // v in {0,4}, u = 1..3: 6 paired cells (weight 2)
    #pragma unroll
    for (int u = 1; u <= 3; u++) {
        acc2 += cell(Zr[u][0], Zi[u][0], Zr[8-u][0], Zi[8-u][0]);
        acc2 += cell(Zr[u][4], Zi[u][4], Zr[8-u][4], Zi[8-u][4]);
    }
    float acc = fmaf(2.0f, acc2, acc1);

    // ---- deterministic reduction: warp -> block -> last-block-done global ----
    #pragma unroll
    for (int o = 16; o > 0; o >>= 1)
        acc += __shfl_xor_sync(FULLM, acc, o);

    __shared__ float smw[BLOCK / 32];
    __shared__ bool isLast;
    if ((threadIdx.x & 31) == 0) smw[threadIdx.x >> 5] = acc;
    __syncthreads();
    if (threadIdx.x == 0) {
        float s = 0.0f;
        #pragma unroll
        for (int i = 0; i < BLOCK / 32; i++) s += smw[i];
        g_partials[blockIdx.x] = s;
        __threadfence();
        unsigned old = atomicInc(&g_count, NBLOCKS - 1);  // wraps to 0 on last
        isLast = (old == NBLOCKS - 1);
    }
    __syncthreads();

    if (isLast) {
        float a = 0.0f;
        #pragma unroll
        for (int i = 0; i < NBLOCKS / BLOCK; i++)
            a += __ldcg(&g_partials[threadIdx.x + i * BLOCK]);
        #pragma unroll
        for (int o = 16; o > 0; o >>= 1)
            a += __shfl_xor_sync(FULLM, a, o);
        if ((threadIdx.x & 31) == 0) smw[threadIdx.x >> 5] = a;
        __syncthreads();
        if (threadIdx.x == 0) {
            float s = 0.0f;
            #pragma unroll
            for (int i = 0; i < BLOCK / 32; i++) s += smw[i];
            out[0] = s * FINAL_SCALE;
        }
    }
}

extern "C" void kernel_launch(void* const* d_in, const int* in_sizes, int n_in,
                              void* d_out, int out_size)
{
    const float* inp = (const float*)d_in[0];
    const float* tgt = (const float*)d_in[1];
    patch_fft_loss_kernel<<<NBLOCKS, BLOCK>>>(inp, tgt, (float*)d_out);
}

// round 6
// speedup vs baseline: 1.5117x; 1.0259x over previous
#include <cuda_runtime.h>
#include <cuda_bf16.h>

// PatchFFTLoss round 6: 1 thread per patch, all 32 LDG.128 front-batched
// (MLP=32/thread) to saturate DRAM at low occupancy. Zero shuffles.
//  - z = (input + i*target)/16, 8 row FFTs + 8 column FFTs in registers.
//  - Hermitian separation; conjugate symmetry halves the epilogue; the 4
//    self-conjugate bins simplify to (g(2Re)-g(2Im))^2.
//  - fused last-block-done reduction, bit-deterministic, graph-capturable.

#define NPATCH   (16 * 3 * 64 * 64)       // 196608
#define BLOCK    128
#define NBLOCKS  (NPATCH / BLOCK)         // 1536
#define LN2      0.69314718055994530942f
#define FINAL_SCALE ((LN2 * LN2) / 12582912.0f)
#define FULLM    0xffffffffu

__device__ float g_partials[NBLOCKS];
__device__ unsigned int g_count = 0;

__device__ __forceinline__ float sgnlg2(float x) {
    return copysignf(__log2f(1.0f + fabsf(x)), x);
}

// paired loss cell: Z at (u,v), Zn at (-u,-v)
__device__ __forceinline__ float cell(float Zr_, float Zi_, float Znr, float Zni) {
    float fir = Zr_ + Znr;
    float fii = Zi_ - Zni;
    float ftr = Zi_ + Zni;
    float fti = Znr - Zr_;
    float d1 = sgnlg2(fir) - sgnlg2(ftr);
    float d2 = sgnlg2(fii) - sgnlg2(fti);
    return fmaf(d1, d1, d2 * d2);
}

// self-conjugate cell: Fi = 2 Re Z, Ft = 2 Im Z, imag parts exactly 0
__device__ __forceinline__ float cell_self(float Zr_, float Zi_) {
    float d1 = sgnlg2(2.0f * Zr_) - sgnlg2(2.0f * Zi_);
    return d1 * d1;
}

// in-place 8-pt complex FFT, natural-order bins (validated rounds 2-5)
__device__ __forceinline__ void fft8(
    float& x0r, float& x1r, float& x2r, float& x3r,
    float& x4r, float& x5r, float& x6r, float& x7r,
    float& x0i, float& x1i, float& x2i, float& x3i,
    float& x4i, float& x5i, float& x6i, float& x7i)
{
    const float C = 0.70710678118654752440f;
    float A0r=x0r+x4r, A0i=x0i+x4i;
    float A1r=x1r+x5r, A1i=x1i+x5i;
    float A2r=x2r+x6r, A2i=x2i+x6i;
    float A3r=x3r+x7r, A3i=x3i+x7i;
    float B0r=x0r-x4r, B0i=x0i-x4i;
    float d1r=x1r-x5r, d1i=x1i-x5i;
    float B1r=C*(d1r+d1i), B1i=C*(d1i-d1r);
    float B2r=x2i-x6i,     B2i=x6r-x2r;
    float d3r=x3r-x7r, d3i=x3i-x7i;
    float B3r=C*(d3i-d3r), B3i=-C*(d3r+d3i);

    float A20r=A0r+A2r, A20i=A0i+A2i;
    float A22r=A0r-A2r, A22i=A0i-A2i;
    float A21r=A1r+A3r, A21i=A1i+A3i;
    float A23r=A1i-A3i, A23i=A3r-A1r;
    float B20r=B0r+B2r, B20i=B0i+B2i;
    float B22r=B0r-B2r, B22i=B0i-B2i;
    float B21r=B1r+B3r, B21i=B1i+B3i;
    float B23r=B1i-B3i, B23i=B3r-B1r;

    x0r=A20r+A21r; x0i=A20i+A21i;
    x4r=A20r-A21r; x4i=A20i-A21i;
    x2r=A22r+A23r; x2i=A22i+A23i;
    x6r=A22r-A23r; x6i=A22i-A23i;
    x1r=B20r+B21r; x1i=B20i+B21i;
    x5r=B20r-B21r; x5i=B20i-B21i;
    x3r=B22r+B23r; x3i=B22i+B23i;
    x7r=B22r-B23r; x7i=B22i-B23i;
}

__global__ void __launch_bounds__(BLOCK, 3)
patch_fft_loss_kernel(const float* __restrict__ inp,
                      const float* __restrict__ tgt,
                      float* __restrict__ out)
{
    const int p  = blockIdx.x * BLOCK + threadIdx.x;   // patch index
    const int pw = p & 63;
    const int ph = (p >> 6) & 63;
    const int bc = p >> 12;
    const size_t base = ((size_t)(bc * 512 + ph * 8)) * 512 + (size_t)pw * 8;

    // ---- phase 0: issue ALL 32 LDG.128 before any arithmetic (MLP=32) ----
    float4 ia[8], ib[8], ta[8], tb[8];
    #pragma unroll
    for (int r = 0; r < 8; r++) {
        const float* ip = inp + base + (size_t)r * 512;
        ia[r] = *(const float4*)(ip);
        ib[r] = *(const float4*)(ip + 4);
    }
    #pragma unroll
    for (int r = 0; r < 8; r++) {
        const float* tp = tgt + base + (size_t)r * 512;
        ta[r] = *(const float4*)(tp);
        tb[r] = *(const float4*)(tp + 4);
    }

    // ---- phase 1: scale + row FFTs (raw float4s retire into Z in place) ----
    float Zr[8][8], Zi[8][8];
    #pragma unroll
    for (int r = 0; r < 8; r++) {
        Zr[r][0]=ia[r].x*0.0625f; Zr[r][1]=ia[r].y*0.0625f;
        Zr[r][2]=ia[r].z*0.0625f; Zr[r][3]=ia[r].w*0.0625f;
        Zr[r][4]=ib[r].x*0.0625f; Zr[r][5]=ib[r].y*0.0625f;
        Zr[r][6]=ib[r].z*0.0625f; Zr[r][7]=ib[r].w*0.0625f;
        Zi[r][0]=ta[r].x*0.0625f; Zi[r][1]=ta[r].y*0.0625f;
        Zi[r][2]=ta[r].z*0.0625f; Zi[r][3]=ta[r].w*0.0625f;
        Zi[r][4]=tb[r].x*0.0625f; Zi[r][5]=tb[r].y*0.0625f;
        Zi[r][6]=tb[r].z*0.0625f; Zi[r][7]=tb[r].w*0.0625f;
        fft8(Zr[r][0],Zr[r][1],Zr[r][2],Zr[r][3],Zr[r][4],Zr[r][5],Zr[r][6],Zr[r][7],
             Zi[r][0],Zi[r][1],Zi[r][2],Zi[r][3],Zi[r][4],Zi[r][5],Zi[r][6],Zi[r][7]);
    }

    // ---- phase 2: column FFTs ----
    #pragma unroll
    for (int v = 0; v < 8; v++) {
        fft8(Zr[0][v],Zr[1][v],Zr[2][v],Zr[3][v],Zr[4][v],Zr[5][v],Zr[6][v],Zr[7][v],
             Zi[0][v],Zi[1][v],Zi[2][v],Zi[3][v],Zi[4][v],Zi[5][v],Zi[6][v],Zi[7][v]);
    }

    // ---- phase 3: Hermitian separation + loss over canonical half ----
    float acc1 = 0.0f, acc2 = 0.0f;
    acc1 += cell_self(Zr[0][0], Zi[0][0]);
    acc1 += cell_self(Zr[0][4], Zi[0][4]);
    acc1 += cell_self(Zr[4][0], Zi[4][0]);
    acc1 += cell_self(Zr[4][4], Zi[4][4]);
    #pragma unroll
    for (int v = 1; v <= 3; v++) {
        #pragma unroll
        for (int u = 0; u < 8; u++) {
            const int un = (8 - u) & 7;
            const int vn = 8 - v;
            acc2 += cell(Zr[u][v], Zi[u][v], Zr[un][vn], Zi[un][vn]);
        }
    }
    #pragma unroll
    for (int u = 1; u <= 3; u++) {
        acc2 += cell(Zr[u][0], Zi[u][0], Zr[8-u][0], Zi[8-u][0]);
        acc2 += cell(Zr[u][4], Zi[u][4], Zr[8-u][4], Zi[8-u][4]);
    }
    float acc = fmaf(2.0f, acc2, acc1);

    // ---- deterministic reduction: warp -> block -> last-block-done global ----
    #pragma unroll
    for (int o = 16; o > 0; o >>= 1)
        acc += __shfl_xor_sync(FULLM, acc, o);

    __shared__ float smw[BLOCK / 32];
    __shared__ bool isLast;
    if ((threadIdx.x & 31) == 0) smw[threadIdx.x >> 5] = acc;
    __syncthreads();
    if (threadIdx.x == 0) {
        float s = 0.0f;
        #pragma unroll
        for (int i = 0; i < BLOCK / 32; i++) s += smw[i];
        g_partials[blockIdx.x] = s;
        __threadfence();
        unsigned old = atomicInc(&g_count, NBLOCKS - 1);  // wraps to 0 on last
        isLast = (old == NBLOCKS - 1);
    }
    __syncthreads();

    if (isLast) {
        float a = 0.0f;
        #pragma unroll
        for (int i = 0; i < NBLOCKS / BLOCK; i++)
            a += __ldcg(&g_partials[threadIdx.x + i * BLOCK]);
        #pragma unroll
        for (int o = 16; o > 0; o >>= 1)
            a += __shfl_xor_sync(FULLM, a, o);
        if ((threadIdx.x & 31) == 0) smw[threadIdx.x >> 5] = a;
        __syncthreads();
        if (threadIdx.x == 0) {
            float s = 0.0f;
            #pragma unroll
            for (int i = 0; i < BLOCK / 32; i++) s += smw[i];
            out[0] = s * FINAL_SCALE;
        }
    }
}

extern "C" void kernel_launch(void* const* d_in, const int* in_sizes, int n_in,
                              void* d_out, int out_size)
{
    const float* inp = (const float*)d_in[0];
    const float* tgt = (const float*)d_in[1];
    patch_fft_loss_kernel<<<NBLOCKS, BLOCK>>>(inp, tgt, (float*)d_out);
}

// round 7
// speedup vs baseline: 1.5943x; 1.0546x over previous
#include <cuda_runtime.h>
#include <cuda_bf16.h>

// PatchFFTLoss round 7: thread pair = (input, target) of the SAME patch.
//  - each thread does a REAL-input 8x8 FFT: real row FFTs keep v=0..4 only
//    (Hermitian in v) -> 64 floats of state (vs 128 packed-complex).
//  - column FFTs: real for v in {0,4}, complex for v in {1,2,3}.
//  - loss: per-bin g = sign*log2(1+|.|); diff across the thread pair via one
//    xor-1 shuffle per g. Both lanes accumulate identical d^2 -> scale /2.
//  - conjugate symmetry: canonical bins only (weights 1 and 2).
//  - fused last-block-done reduction, bit-deterministic, graph-capturable.

#define NPATCH   (16 * 3 * 64 * 64)       // 196608
#define NTHREADS (NPATCH * 2)             // 393216
#define BLOCK    128
#define NBLOCKS  (NTHREADS / BLOCK)       // 3072
#define LN2      0.69314718055994530942f
#define FINAL_SCALE ((LN2 * LN2) / (2.0f * 12582912.0f))
#define FULLM    0xffffffffu

__device__ float g_partials[NBLOCKS];
__device__ unsigned int g_count = 0;

__device__ __forceinline__ float sgnlg2(float x) {
    return copysignf(__log2f(1.0f + fabsf(x)), x);
}

// squared difference of g across the (input,target) thread pair
__device__ __forceinline__ float dsq(float gv) {
    float gp = __shfl_xor_sync(FULLM, gv, 1);
    float d = gv - gp;
    return d * d;
}

// complex 8-pt FFT in place, natural-order bins (validated rounds 2-6)
__device__ __forceinline__ void fft8c(float* xr, float* xi)
{
    const float C = 0.70710678118654752440f;
    float A0r=xr[0]+xr[4], A0i=xi[0]+xi[4];
    float A1r=xr[1]+xr[5], A1i=xi[1]+xi[5];
    float A2r=xr[2]+xr[6], A2i=xi[2]+xi[6];
    float A3r=xr[3]+xr[7], A3i=xi[3]+xi[7];
    float B0r=xr[0]-xr[4], B0i=xi[0]-xi[4];
    float d1r=xr[1]-xr[5], d1i=xi[1]-xi[5];
    float B1r=C*(d1r+d1i), B1i=C*(d1i-d1r);
    float B2r=xi[2]-xi[6], B2i=xr[6]-xr[2];
    float d3r=xr[3]-xr[7], d3i=xi[3]-xi[7];
    float B3r=C*(d3i-d3r), B3i=-C*(d3r+d3i);

    float A20r=A0r+A2r, A20i=A0i+A2i;
    float A22r=A0r-A2r, A22i=A0i-A2i;
    float A21r=A1r+A3r, A21i=A1i+A3i;
    float A23r=A1i-A3i, A23i=A3r-A1r;
    float B20r=B0r+B2r, B20i=B0i+B2i;
    float B22r=B0r-B2r, B22i=B0i-B2i;
    float B21r=B1r+B3r, B21i=B1i+B3i;
    float B23r=B1i-B3i, B23i=B3r-B1r;

    xr[0]=A20r+A21r; xi[0]=A20i+A21i;
    xr[4]=A20r-A21r; xi[4]=A20i-A21i;
    xr[2]=A22r+A23r; xi[2]=A22i+A23i;
    xr[6]=A22r-A23r; xi[6]=A22i-A23i;
    xr[1]=B20r+B21r; xi[1]=B20i+B21i;
    xr[5]=B20r-B21r; xi[5]=B20i-B21i;
    xr[3]=B22r+B23r; xi[3]=B22i+B23i;
    xr[7]=B22r-B23r; xi[7]=B22i-B23i;
}

__global__ void __launch_bounds__(BLOCK, 4)
patch_fft_loss_kernel(const float* __restrict__ inp,
                      const float* __restrict__ tgt,
                      float* __restrict__ out)
{
    const int gid = blockIdx.x * BLOCK + threadIdx.x;
    const int t  = gid & 1;           // 0 = input, 1 = target
    const int p  = gid >> 1;          // patch index
    const int pw = p & 63;
    const int ph = (p >> 6) & 63;
    const int bc = p >> 12;
    const float* __restrict__ src = t ? tgt : inp;
    const size_t base = ((size_t)(bc * 512 + ph * 8)) * 512 + (size_t)pw * 8;

    const float C = 0.70710678118654752440f;
    const float S = 0.125f;           // ortho norm 1/8

    // ---- front-batched loads: 16 LDG.128 ----
    float4 la[8], lb[8];
    #pragma unroll
    for (int r = 0; r < 8; r++) {
        const float* rp = src + base + (size_t)r * 512;
        la[r] = *(const float4*)(rp);
        lb[r] = *(const float4*)(rp + 4);
    }

    // ---- real row FFTs: keep v = 0..4 (v0, v4 real) ----
    float R0[8], R4[8];                       // v=0, v=4 (real)
    float X1r[8], X1i[8], X2r[8], X2i[8], X3r[8], X3i[8];
    #pragma unroll
    for (int r = 0; r < 8; r++) {
        float x0=la[r].x*S, x1=la[r].y*S, x2=la[r].z*S, x3=la[r].w*S;
        float x4=lb[r].x*S, x5=lb[r].y*S, x6=lb[r].z*S, x7=lb[r].w*S;
        float a04p=x0+x4, a04m=x0-x4;
        float a26p=x2+x6, a26m=x2-x6;
        float E0=a04p+a26p, E2=a04p-a26p;
        float b15p=x1+x5, b15m=x1-x5;
        float b37p=x3+x7, b37m=x3-x7;
        float O0=b15p+b37p, O2=b15p-b37p;
        float t1 =  C*(b15m-b37m);
        float t2 = -C*(b15m+b37m);
        R0[r]  = E0 + O0;
        R4[r]  = E0 - O0;
        X1r[r] = a04m + t1;  X1i[r] = -a26m + t2;
        X2r[r] = E2;         X2i[r] = -O2;
        X3r[r] = a04m - t1;  X3i[r] =  a26m + t2;
    }

    float acc1 = 0.0f, acc2 = 0.0f;

    // ---- columns v = 0 and v = 4: real FFT, bins u = 0..4 ----
    #pragma unroll
    for (int k = 0; k < 2; k++) {
        const float* c = k ? R4 : R0;
        float a04p=c[0]+c[4], a04m=c[0]-c[4];
        float a26p=c[2]+c[6], a26m=c[2]-c[6];
        float E0=a04p+a26p, E2=a04p-a26p;
        float b15p=c[1]+c[5], b15m=c[1]-c[5];
        float b37p=c[3]+c[7], b37m=c[3]-c[7];
        float O0=b15p+b37p, O2=b15p-b37p;
        float t1 =  C*(b15m-b37m);
        float t2 = -C*(b15m+b37m);
        // u=0,4 self-conjugate (imag exactly 0): weight 1, real diff only
        acc1 += dsq(sgnlg2(E0 + O0));
        acc1 += dsq(sgnlg2(E0 - O0));
        // u=1..3: weight 2
        acc2 += dsq(sgnlg2(a04m + t1)) + dsq(sgnlg2(-a26m + t2));
        acc2 += dsq(sgnlg2(E2))        + dsq(sgnlg2(-O2));
        acc2 += dsq(sgnlg2(a04m - t1)) + dsq(sgnlg2( a26m + t2));
    }

    // ---- columns v = 1..3: complex FFT, all u, weight 2 ----
    fft8c(X1r, X1i);
    #pragma unroll
    for (int u = 0; u < 8; u++)
        acc2 += dsq(sgnlg2(X1r[u])) + dsq(sgnlg2(X1i[u]));
    fft8c(X2r, X2i);
    #pragma unroll
    for (int u = 0; u < 8; u++)
        acc2 += dsq(sgnlg2(X2r[u])) + dsq(sgnlg2(X2i[u]));
    fft8c(X3r, X3i);
    #pragma unroll
    for (int u = 0; u < 8; u++)
        acc2 += dsq(sgnlg2(X3r[u])) + dsq(sgnlg2(X3i[u]));

    float acc = fmaf(2.0f, acc2, acc1);

    // ---- deterministic reduction: warp -> block -> last-block-done global ----
    #pragma unroll
    for (int o = 16; o > 0; o >>= 1)
        acc += __shfl_xor_sync(FULLM, acc, o);

    __shared__ float smw[BLOCK / 32];
    __shared__ bool isLast;
    if ((threadIdx.x & 31) == 0) smw[threadIdx.x >> 5] = acc;
    __syncthreads();
    if (threadIdx.x == 0) {
        float s = 0.0f;
        #pragma unroll
        for (int i = 0; i < BLOCK / 32; i++) s += smw[i];
        g_partials[blockIdx.x] = s;
        __threadfence();
        unsigned old = atomicInc(&g_count, NBLOCKS - 1);  // wraps to 0 on last
        isLast = (old == NBLOCKS - 1);
    }
    __syncthreads();

    if (isLast) {
        float a = 0.0f;
        #pragma unroll
        for (int i = 0; i < NBLOCKS / BLOCK; i++)
            a += __ldcg(&g_partials[threadIdx.x + i * BLOCK]);
        #pragma unroll
        for (int o = 16; o > 0; o >>= 1)
            a += __shfl_xor_sync(FULLM, a, o);
        if ((threadIdx.x & 31) == 0) smw[threadIdx.x >> 5] = a;
        __syncthreads();
        if (threadIdx.x == 0) {
            float s = 0.0f;
            #pragma unroll
            for (int i = 0; i < BLOCK / 32; i++) s += smw[i];
            out[0] = s * FINAL_SCALE;
        }
    }
}

extern "C" void kernel_launch(void* const* d_in, const int* in_sizes, int n_in,
                              void* d_out, int out_size)
{
    const float* inp = (const float*)d_in[0];
    const float* tgt = (const float*)d_in[1];
    patch_fft_loss_kernel<<<NBLOCKS, BLOCK>>>(inp, tgt, (float*)d_out);
}

// round 8
// speedup vs baseline: 1.7602x; 1.1041x over previous
#include <cuda_runtime.h>
#include <cuda_bf16.h>

// PatchFFTLoss round 8: round-7 algorithm (thread pair = input/target of the
// same patch, real-input 8x8 FFT, Hermitian-in-v, epilogue pair-diff via
// xor-1 shuffles) with the register budget forced to 85 (6 CTAs/SM) to lift
// occupancy from 22% to ~37%. Latency-bound kernel: time ~ 1/warps.

#define NPATCH   (16 * 3 * 64 * 64)       // 196608
#define NTHREADS (NPATCH * 2)             // 393216
#define BLOCK    128
#define NBLOCKS  (NTHREADS / BLOCK)       // 3072
#define LN2      0.69314718055994530942f
#define FINAL_SCALE ((LN2 * LN2) / (2.0f * 12582912.0f))
#define FULLM    0xffffffffu

__device__ float g_partials[NBLOCKS];
__device__ unsigned int g_count = 0;

__device__ __forceinline__ float sgnlg2(float x) {
    return copysignf(__log2f(1.0f + fabsf(x)), x);
}

// squared difference of g across the (input,target) thread pair
__device__ __forceinline__ float dsq(float gv) {
    float gp = __shfl_xor_sync(FULLM, gv, 1);
    float d = gv - gp;
    return d * d;
}

// complex 8-pt FFT in place, natural-order bins (validated rounds 2-7)
__device__ __forceinline__ void fft8c(float* xr, float* xi)
{
    const float C = 0.70710678118654752440f;
    float A0r=xr[0]+xr[4], A0i=xi[0]+xi[4];
    float A1r=xr[1]+xr[5], A1i=xi[1]+xi[5];
    float A2r=xr[2]+xr[6], A2i=xi[2]+xi[6];
    float A3r=xr[3]+xr[7], A3i=xi[3]+xi[7];
    float B0r=xr[0]-xr[4], B0i=xi[0]-xi[4];
    float d1r=xr[1]-xr[5], d1i=xi[1]-xi[5];
    float B1r=C*(d1r+d1i), B1i=C*(d1i-d1r);
    float B2r=xi[2]-xi[6], B2i=xr[6]-xr[2];
    float d3r=xr[3]-xr[7], d3i=xi[3]-xi[7];
    float B3r=C*(d3i-d3r), B3i=-C*(d3r+d3i);

    float A20r=A0r+A2r, A20i=A0i+A2i;
    float A22r=A0r-A2r, A22i=A0i-A2i;
    float A21r=A1r+A3r, A21i=A1i+A3i;
    float A23r=A1i-A3i, A23i=A3r-A1r;
    float B20r=B0r+B2r, B20i=B0i+B2i;
    float B22r=B0r-B2r, B22i=B0i-B2i;
    float B21r=B1r+B3r, B21i=B1i+B3i;
    float B23r=B1i-B3i, B23i=B3r-B1r;

    xr[0]=A20r+A21r; xi[0]=A20i+A21i;
    xr[4]=A20r-A21r; xi[4]=A20i-A21i;
    xr[2]=A22r+A23r; xi[2]=A22i+A23i;
    xr[6]=A22r-A23r; xi[6]=A22i-A23i;
    xr[1]=B20r+B21r; xi[1]=B20i+B21i;
    xr[5]=B20r-B21r; xi[5]=B20i-B21i;
    xr[3]=B22r+B23r; xi[3]=B22i+B23i;
    xr[7]=B22r-B23r; xi[7]=B22i-B23i;
}

__global__ void __launch_bounds__(BLOCK, 6)
patch_fft_loss_kernel(const float* __restrict__ inp,
                      const float* __restrict__ tgt,
                      float* __restrict__ out)
{
    const int gid = blockIdx.x * BLOCK + threadIdx.x;
    const int t  = gid & 1;           // 0 = input, 1 = target
    const int p  = gid >> 1;          // patch index
    const int pw = p & 63;
    const int ph = (p >> 6) & 63;
    const int bc = p >> 12;
    const float* __restrict__ src = t ? tgt : inp;
    const size_t base = ((size_t)(bc * 512 + ph * 8)) * 512 + (size_t)pw * 8;

    const float C = 0.70710678118654752440f;
    const float S = 0.125f;           // ortho norm 1/8

    // ---- front-batched loads: 16 LDG.128 ----
    float4 la[8], lb[8];
    #pragma unroll
    for (int r = 0; r < 8; r++) {
        const float* rp = src + base + (size_t)r * 512;
        la[r] = *(const float4*)(rp);
        lb[r] = *(const float4*)(rp + 4);
    }

    // ---- real row FFTs: keep v = 0..4 (v0, v4 real) ----
    float R0[8], R4[8];                       // v=0, v=4 (real)
    float X1r[8], X1i[8], X2r[8], X2i[8], X3r[8], X3i[8];
    #pragma unroll
    for (int r = 0; r < 8; r++) {
        float x0=la[r].x*S, x1=la[r].y*S, x2=la[r].z*S, x3=la[r].w*S;
        float x4=lb[r].x*S, x5=lb[r].y*S, x6=lb[r].z*S, x7=lb[r].w*S;
        float a04p=x0+x4, a04m=x0-x4;
        float a26p=x2+x6, a26m=x2-x6;
        float E0=a04p+a26p, E2=a04p-a26p;
        float b15p=x1+x5, b15m=x1-x5;
        float b37p=x3+x7, b37m=x3-x7;
        float O0=b15p+b37p, O2=b15p-b37p;
        float t1 =  C*(b15m-b37m);
        float t2 = -C*(b15m+b37m);
        R0[r]  = E0 + O0;
        R4[r]  = E0 - O0;
        X1r[r] = a04m + t1;  X1i[r] = -a26m + t2;
        X2r[r] = E2;         X2i[r] = -O2;
        X3r[r] = a04m - t1;  X3i[r] =  a26m + t2;
    }

    float acc1 = 0.0f, acc2 = 0.0f;

    // ---- columns v = 0 and v = 4: real FFT, bins u = 0..4 ----
    #pragma unroll
    for (int k = 0; k < 2; k++) {
        const float* c = k ? R4 : R0;
        float a04p=c[0]+c[4], a04m=c[0]-c[4];
        float a26p=c[2]+c[6], a26m=c[2]-c[6];
        float E0=a04p+a26p, E2=a04p-a26p;
        float b15p=c[1]+c[5], b15m=c[1]-c[5];
        float b37p=c[3]+c[7], b37m=c[3]-c[7];
        float O0=b15p+b37p, O2=b15p-b37p;
        float t1 =  C*(b15m-b37m);
        float t2 = -C*(b15m+b37m);
        // u=0,4 self-conjugate (imag exactly 0): weight 1, real diff only
        acc1 += dsq(sgnlg2(E0 + O0));
        acc1 += dsq(sgnlg2(E0 - O0));
        // u=1..3: weight 2
        acc2 += dsq(sgnlg2(a04m + t1)) + dsq(sgnlg2(-a26m + t2));
        acc2 += dsq(sgnlg2(E2))        + dsq(sgnlg2(-O2));
        acc2 += dsq(sgnlg2(a04m - t1)) + dsq(sgnlg2( a26m + t2));
    }

    // ---- columns v = 1..3: complex FFT, all u, weight 2 ----
    fft8c(X1r, X1i);
    #pragma unroll
    for (int u = 0; u < 8; u++)
        acc2 += dsq(sgnlg2(X1r[u])) + dsq(sgnlg2(X1i[u]));
    fft8c(X2r, X2i);
    #pragma unroll
    for (int u = 0; u < 8; u++)
        acc2 += dsq(sgnlg2(X2r[u])) + dsq(sgnlg2(X2i[u]));
    fft8c(X3r, X3i);
    #pragma unroll
    for (int u = 0; u < 8; u++)
        acc2 += dsq(sgnlg2(X3r[u])) + dsq(sgnlg2(X3i[u]));

    float acc = fmaf(2.0f, acc2, acc1);

    // ---- deterministic reduction: warp -> block -> last-block-done global ----
    #pragma unroll
    for (int o = 16; o > 0; o >>= 1)
        acc += __shfl_xor_sync(FULLM, acc, o);

    __shared__ float smw[BLOCK / 32];
    __shared__ bool isLast;
    if ((threadIdx.x & 31) == 0) smw[threadIdx.x >> 5] = acc;
    __syncthreads();
    if (threadIdx.x == 0) {
        float s = 0.0f;
        #pragma unroll
        for (int i = 0; i < BLOCK / 32; i++) s += smw[i];
        g_partials[blockIdx.x] = s;
        __threadfence();
        unsigned old = atomicInc(&g_count, NBLOCKS - 1);  // wraps to 0 on last
        isLast = (old == NBLOCKS - 1);
    }
    __syncthreads();

    if (isLast) {
        float a = 0.0f;
        #pragma unroll
        for (int i = 0; i < NBLOCKS / BLOCK; i++)
            a += __ldcg(&g_partials[threadIdx.x + i * BLOCK]);
        #pragma unroll
        for (int o = 16; o > 0; o >>= 1)
            a += __shfl_xor_sync(FULLM, a, o);
        if ((threadIdx.x & 31) == 0) smw[threadIdx.x >> 5] = a;
        __syncthreads();
        if (threadIdx.x == 0) {
            float s = 0.0f;
            #pragma unroll
            for (int i = 0; i < BLOCK / 32; i++) s += smw[i];
            out[0] = s * FINAL_SCALE;
        }
    }
}

extern "C" void kernel_launch(void* const* d_in, const int* in_sizes, int n_in,
                              void* d_out, int out_size)
{
    const float* inp = (const float*)d_in[0];
    const float* tgt = (const float*)d_in[1];
    patch_fft_loss_kernel<<<NBLOCKS, BLOCK>>>(inp, tgt, (float*)d_out);
}

// round 9
// speedup vs baseline: 1.7790x; 1.0107x over previous
#include <cuda_runtime.h>
#include <cuda_bf16.h>

// PatchFFTLoss round 9: R8 structure (thread pair = input/target of the same
// patch, real-input 8x8 FFT, Hermitian-in-v, pair-diff epilogue) plus:
//  - ortho scale folded into the log: g = copysign(log2(fma(1/8,|y|,1)), y)
//    on the UNNORMALIZED FFT -> all 64 input scale FMULs removed.
//  - f32x2 packed arithmetic (sm_103a FFMA2 path): row FFTs packed over
//    row pairs; X1/X2 column FFTs packed over the v dimension.

#define NPATCH   (16 * 3 * 64 * 64)       // 196608
#define NTHREADS (NPATCH * 2)             // 393216
#define BLOCK    128
#define NBLOCKS  (NTHREADS / BLOCK)       // 3072
#define LN2      0.69314718055994530942f
#define FINAL_SCALE ((LN2 * LN2) / (2.0f * 12582912.0f))
#define FULLM    0xffffffffu

__device__ float g_partials[NBLOCKS];
__device__ unsigned int g_count = 0;

typedef unsigned long long u64;

__device__ __forceinline__ u64 pk(float lo, float hi) {
    u64 r; asm("mov.b64 %0, {%1, %2};" : "=l"(r) : "f"(lo), "f"(hi)); return r;
}
__device__ __forceinline__ void upk(u64 v, float& lo, float& hi) {
    asm("mov.b64 {%0, %1}, %2;" : "=f"(lo), "=f"(hi) : "l"(v));
}
__device__ __forceinline__ u64 add2(u64 a, u64 b) {
    u64 r; asm("add.rn.f32x2 %0, %1, %2;" : "=l"(r) : "l"(a), "l"(b)); return r;
}
__device__ __forceinline__ u64 sub2(u64 a, u64 b) {
    u64 r; asm("sub.rn.f32x2 %0, %1, %2;" : "=l"(r) : "l"(a), "l"(b)); return r;
}
__device__ __forceinline__ u64 mul2(u64 a, u64 b) {
    u64 r; asm("mul.rn.f32x2 %0, %1, %2;" : "=l"(r) : "l"(a), "l"(b)); return r;
}

// g on unnormalized FFT value: sign(x) * log2(1 + |x|/8)
__device__ __forceinline__ float gfun(float x) {
    return copysignf(__log2f(fmaf(0.125f, fabsf(x), 1.0f)), x);
}

// squared difference of g across the (input,target) thread pair
__device__ __forceinline__ float dsq(float gv) {
    float gp = __shfl_xor_sync(FULLM, gv, 1);
    float d = gv - gp;
    return d * d;
}

// scalar complex 8-pt FFT in place, natural-order bins (validated r2-r8)
__device__ __forceinline__ void fft8c(float* xr, float* xi)
{
    const float C = 0.70710678118654752440f;
    float A0r=xr[0]+xr[4], A0i=xi[0]+xi[4];
    float A1r=xr[1]+xr[5], A1i=xi[1]+xi[5];
    float A2r=xr[2]+xr[6], A2i=xi[2]+xi[6];
    float A3r=xr[3]+xr[7], A3i=xi[3]+xi[7];
    float B0r=xr[0]-xr[4], B0i=xi[0]-xi[4];
    float d1r=xr[1]-xr[5], d1i=xi[1]-xi[5];
    float B1r=C*(d1r+d1i), B1i=C*(d1i-d1r);
    float B2r=xi[2]-xi[6], B2i=xr[6]-xr[2];
    float d3r=xr[3]-xr[7], d3i=xi[3]-xi[7];
    float B3r=C*(d3i-d3r), B3i=-C*(d3r+d3i);

    float A20r=A0r+A2r, A20i=A0i+A2i;
    float A22r=A0r-A2r, A22i=A0i-A2i;
    float A21r=A1r+A3r, A21i=A1i+A3i;
    float A23r=A1i-A3i, A23i=A3r-A1r;
    float B20r=B0r+B2r, B20i=B0i+B2i;
    float B22r=B0r-B2r, B22i=B0i-B2i;
    float B21r=B1r+B3r, B21i=B1i+B3i;
    float B23r=B1i-B3i, B23i=B3r-B1r;

    xr[0]=A20r+A21r; xi[0]=A20i+A21i;
    xr[4]=A20r-A21r; xi[4]=A20i-A21i;
    xr[2]=A22r+A23r; xi[2]=A22i+A23i;
    xr[6]=A22r-A23r; xi[6]=A22i-A23i;
    xr[1]=B20r+B21r; xi[1]=B20i+B21i;
    xr[5]=B20r-B21r; xi[5]=B20i-B21i;
    xr[3]=B22r+B23r; xi[3]=B22i+B23i;
    xr[7]=B22r-B23r; xi[7]=B22i-B23i;
}

// packed complex 8-pt FFT: each u64 holds the same butterfly slot of TWO
// independent FFTs (here columns v=1 and v=2). Same network as fft8c.
__device__ __forceinline__ void fft8c2(u64* xr, u64* xi, u64 CC, u64 MCC)
{
    u64 A0r=add2(xr[0],xr[4]), A0i=add2(xi[0],xi[4]);
    u64 A1r=add2(xr[1],xr[5]), A1i=add2(xi[1],xi[5]);
    u64 A2r=add2(xr[2],xr[6]), A2i=add2(xi[2],xi[6]);
    u64 A3r=add2(xr[3],xr[7]), A3i=add2(xi[3],xi[7]);
    u64 B0r=sub2(xr[0],xr[4]), B0i=sub2(xi[0],xi[4]);
    u64 d1r=sub2(xr[1],xr[5]), d1i=sub2(xi[1],xi[5]);
    u64 B1r=mul2(CC,add2(d1r,d1i)), B1i=mul2(CC,sub2(d1i,d1r));
    u64 B2r=sub2(xi[2],xi[6]),      B2i=sub2(xr[6],xr[2]);
    u64 d3r=sub2(xr[3],xr[7]), d3i=sub2(xi[3],xi[7]);
    u64 B3r=mul2(CC,sub2(d3i,d3r)), B3i=mul2(MCC,add2(d3r,d3i));

    u64 A20r=add2(A0r,A2r), A20i=add2(A0i,A2i);
    u64 A22r=sub2(A0r,A2r), A22i=sub2(A0i,A2i);
    u64 A21r=add2(A1r,A3r), A21i=add2(A1i,A3i);
    u64 A23r=sub2(A1i,A3i), A23i=sub2(A3r,A1r);
    u64 B20r=add2(B0r,B2r), B20i=add2(B0i,B2i);
    u64 B22r=sub2(B0r,B2r), B22i=sub2(B0i,B2i);
    u64 B21r=add2(B1r,B3r), B21i=add2(B1i,B3i);
    u64 B23r=sub2(B1i,B3i), B23i=sub2(B3r,B1r);

    xr[0]=add2(A20r,A21r); xi[0]=add2(A20i,A21i);
    xr[4]=sub2(A20r,A21r); xi[4]=sub2(A20i,A21i);
    xr[2]=add2(A22r,A23r); xi[2]=add2(A22i,A23i);
    xr[6]=sub2(A22r,A23r); xi[6]=sub2(A22i,A23i);
    xr[1]=add2(B20r,B21r); xi[1]=add2(B20i,B21i);
    xr[5]=sub2(B20r,B21r); xi[5]=sub2(B20i,B21i);
    xr[3]=add2(B22r,B23r); xi[3]=add2(B22i,B23i);
    xr[7]=sub2(B22r,B23r); xi[7]=sub2(B22i,B23i);
}

__global__ void __launch_bounds__(BLOCK, 6)
patch_fft_loss_kernel(const float* __restrict__ inp,
                      const float* __restrict__ tgt,
                      float* __restrict__ out)
{
    const int gid = blockIdx.x * BLOCK + threadIdx.x;
    const int t  = gid & 1;           // 0 = input, 1 = target
    const int p  = gid >> 1;          // patch index
    const int pw = p & 63;
    const int ph = (p >> 6) & 63;
    const int bc = p >> 12;
    const float* __restrict__ src = t ? tgt : inp;
    const size_t base = ((size_t)(bc * 512 + ph * 8)) * 512 + (size_t)pw * 8;

    const float C = 0.70710678118654752440f;
    const u64 CC  = pk(C, C);
    const u64 MCC = pk(-C, -C);

    // ---- front-batched loads: 16 LDG.128 ----
    float4 la[8], lb[8];
    #pragma unroll
    for (int r = 0; r < 8; r++) {
        const float* rp = src + base + (size_t)r * 512;
        la[r] = *(const float4*)(rp);
        lb[r] = *(const float4*)(rp + 4);
    }

    // ---- packed real row FFTs: rows (2P, 2P+1) in one f32x2 lane-pair ----
    // outputs per row: R0 (v=0, real), R4 (v=4, real), X1..X3 complex
    float R0[8], R4[8];
    float X1r[8], X1i[8], X2r[8], X2i[8], X3r[8], X3i[8];
    #pragma unroll
    for (int P = 0; P < 4; P++) {
        const int r0 = 2 * P, r1 = 2 * P + 1;
        u64 p0 = pk(la[r0].x, la[r1].x), p1 = pk(la[r0].y, la[r1].y);
        u64 p2 = pk(la[r0].z, la[r1].z), p3 = pk(la[r0].w, la[r1].w);
        u64 p4 = pk(lb[r0].x, lb[r1].x), p5 = pk(lb[r0].y, lb[r1].y);
        u64 p6 = pk(lb[r0].z, lb[r1].z), p7 = pk(lb[r0].w, lb[r1].w);

        u64 a04p = add2(p0, p4), a04m = sub2(p0, p4);
        u64 a26p = add2(p2, p6), a26m = sub2(p2, p6);
        u64 E0 = add2(a04p, a26p), E2 = sub2(a04p, a26p);
        u64 b15p = add2(p1, p5), b15m = sub2(p1, p5);
        u64 b37p = add2(p3, p7), b37m = sub2(p3, p7);
        u64 O0 = add2(b15p, b37p);
        u64 t1 = mul2(CC,  sub2(b15m, b37m));
        u64 t2 = mul2(MCC, add2(b15m, b37m));

        upk(add2(E0, O0),    R0[r0],  R0[r1]);
        upk(sub2(E0, O0),    R4[r0],  R4[r1]);
        upk(add2(a04m, t1),  X1r[r0], X1r[r1]);
        upk(sub2(t2, a26m),  X1i[r0], X1i[r1]);
        upk(E2,              X2r[r0], X2r[r1]);
        upk(sub2(b37p, b15p),X2i[r0], X2i[r1]);   // X2i = -O2
        upk(sub2(a04m, t1),  X3r[r0], X3r[r1]);
        upk(add2(a26m, t2),  X3i[r0], X3i[r1]);
    }

    float acc1 = 0.0f, acc2 = 0.0f;

    // ---- columns v = 0 and v = 4: scalar real FFT, bins u = 0..4 ----
    #pragma unroll
    for (int k = 0; k < 2; k++) {
        const float* c = k ? R4 : R0;
        float a04p=c[0]+c[4], a04m=c[0]-c[4];
        float a26p=c[2]+c[6], a26m=c[2]-c[6];
        float E0=a04p+a26p, E2=a04p-a26p;
        float b15p=c[1]+c[5], b15m=c[1]-c[5];
        float b37p=c[3]+c[7], b37m=c[3]-c[7];
        float O0=b15p+b37p, O2=b15p-b37p;
        float t1 =  C*(b15m-b37m);
        float t2 = -C*(b15m+b37m);
        // u=0,4 self-conjugate (imag exactly 0): weight 1
        acc1 += dsq(gfun(E0 + O0));
        acc1 += dsq(gfun(E0 - O0));
        // u=1..3: weight 2
        acc2 += dsq(gfun(a04m + t1)) + dsq(gfun(-a26m + t2));
        acc2 += dsq(gfun(E2))        + dsq(gfun(-O2));
        acc2 += dsq(gfun(a04m - t1)) + dsq(gfun( a26m + t2));
    }

    // ---- columns v = 1 and v = 2: ONE packed complex FFT (f32x2) ----
    {
        u64 xr[8], xi[8];
        #pragma unroll
        for (int r = 0; r < 8; r++) {
            xr[r] = pk(X1r[r], X2r[r]);
            xi[r] = pk(X1i[r], X2i[r]);
        }
        fft8c2(xr, xi, CC, MCC);
        #pragma unroll
        for (int u = 0; u < 8; u++) {
            float f1, f2, f3, f4;
            upk(xr[u], f1, f2);
            upk(xi[u], f3, f4);
            acc2 += dsq(gfun(f1)) + dsq(gfun(f3));   // v=1: re, im
            acc2 += dsq(gfun(f2)) + dsq(gfun(f4));   // v=2: re, im
        }
    }

    // ---- column v = 3: scalar complex FFT ----
    fft8c(X3r, X3i);
    #pragma unroll
    for (int u = 0; u < 8; u++)
        acc2 += dsq(gfun(X3r[u])) + dsq(gfun(X3i[u]));

    float acc = fmaf(2.0f, acc2, acc1);

    // ---- deterministic reduction: warp -> block -> last-block-done global ----
    #pragma unroll
    for (int o = 16; o > 0; o >>= 1)
        acc += __shfl_xor_sync(FULLM, acc, o);

    __shared__ float smw[BLOCK / 32];
    __shared__ bool isLast;
    if ((threadIdx.x & 31) == 0) smw[threadIdx.x >> 5] = acc;
    __syncthreads();
    if (threadIdx.x == 0) {
        float s = 0.0f;
        #pragma unroll
        for (int i = 0; i < BLOCK / 32; i++) s += smw[i];
        g_partials[blockIdx.x] = s;
        __threadfence();
        unsigned old = atomicInc(&g_count, NBLOCKS - 1);  // wraps to 0 on last
        isLast = (old == NBLOCKS - 1);
    }
    __syncthreads();

    if (isLast) {
        float a = 0.0f;
        #pragma unroll
        for (int i = 0; i < NBLOCKS / BLOCK; i++)
            a += __ldcg(&g_partials[threadIdx.x + i * BLOCK]);
        #pragma unroll
        for (int o = 16; o > 0; o >>= 1)
            a += __shfl_xor_sync(FULLM, a, o);
        if ((threadIdx.x & 31) == 0) smw[threadIdx.x >> 5] = a;
        __syncthreads();
        if (threadIdx.x == 0) {
            float s = 0.0f;
            #pragma unroll
            for (int i = 0; i < BLOCK / 32; i++) s += smw[i];
            out[0] = s * FINAL_SCALE;
        }
    }
}

extern "C" void kernel_launch(void* const* d_in, const int* in_sizes, int n_in,
                              void* d_out, int out_size)
{
    const float* inp = (const float*)d_in[0];
    const float* tgt = (const float*)d_in[1];
    patch_fft_loss_kernel<<<NBLOCKS, BLOCK>>>(inp, tgt, (float*)d_out);
}